// round 3
// baseline (speedup 1.0000x reference)
#include <cuda_runtime.h>

#define BB 16          // batches
#define NN 576         // queries
#define MM 16          // targets
#define DD 81          // classes / emb dim
#define BG 80
#define THR 0.75f
#define NW 18          // warps per block

// Per-block partial outputs (no init needed; fully rewritten each run)
__device__ float g_S[BB][DD];
__device__ float g_P[BB][DD];
__device__ int   g_C[BB][DD];
__device__ float g_ce[BB];
__device__ float g_bb[BB];
__device__ float g_gi[BB];
__device__ unsigned g_tick;   // self-wrapping ticket (atomicInc mod 16)

__global__ void __launch_bounds__(NN) k_all(
    const float* __restrict__ emb,  // [B,N,D]
    const float* __restrict__ cp,   // [B,N,D]
    const float* __restrict__ pb,   // [B,N,4]
    const float* __restrict__ tb,   // [B,M,4]
    const int*   __restrict__ tl,   // [B,M]
    const int*   __restrict__ mi,   // [B,M]
    float* __restrict__ out)
{
    __shared__ float4   sbox[NN];
    __shared__ float    sarea[NN];
    __shared__ int      stc[NN];
    __shared__ unsigned swmin[2][NW];
    __shared__ float    sWS[NW][DD];   // per-warp S slices
    __shared__ float    sWP[NW][DD];   // per-warp P slices
    __shared__ int      sWC[NW][DD];   // per-warp cnt slices
    __shared__ float    sf[3];         // flbg, flfg, cbg
    __shared__ float    sbbv[MM], sggv[MM];
    __shared__ int      slast;
    __shared__ float    racc[3];       // finalize: pc, pos, neg

    const int b    = blockIdx.x;
    const int j    = threadIdx.x;
    const int wid  = j >> 5;
    const int lane = j & 31;

    // ---- load boxes ----
    float4 box = ((const float4*)pb)[b*NN + j];
    sbox[j]  = box;
    float areaj = (box.z - box.x) * (box.w - box.y);
    sarea[j] = areaj;
    stc[j]   = BG;
    if (j < 3) sf[j] = 0.f;
    __syncthreads();

    // tc0 scatter (sequential, last-wins)
    if (j == 0) {
        #pragma unroll
        for (int m = 0; m < MM; m++)
            stc[mi[b*MM + m]] = tl[b*MM + m];
    }
    __syncthreads();

    int my = stc[j];

    // ---- sequential relabel scan: 1 barrier per round ----
    int cur = 0, par = 0;
    while (true) {
        unsigned cand = (j >= cur && my != BG) ? (unsigned)j : (unsigned)NN;
        unsigned wm = __reduce_min_sync(0xffffffffu, cand);
        if (lane == 0) swmin[par][wid] = wm;
        __syncthreads();
        unsigned n = NN;
        #pragma unroll
        for (int w = 0; w < NW; w++) n = min(n, swmin[par][w]);
        if (n >= NN) break;

        int label = stc[n];
        float4 bn = sbox[n];
        float lx = fmaxf(bn.x, box.x), ly = fmaxf(bn.y, box.y);
        float rx = fminf(bn.z, box.z), ry = fminf(bn.w, box.w);
        float w_ = fmaxf(rx - lx, 0.f), h_ = fmaxf(ry - ly, 0.f);
        float inter = w_ * h_;
        float iou = inter / (sarea[(int)n] + areaj - inter);
        if (iou > THR) { my = label; stc[j] = label; }
        cur = (int)n + 1;
        par ^= 1;
    }
    __syncthreads();   // final stc writes visible to everyone

    // ---- bbox L1 + GIoU (matched pairs) ----
    if (j < MM) {
        int idx = mi[b*MM + j];
        float4 s  = sbox[idx];
        float4 tg = ((const float4*)tb)[b*MM + j];
        float l1 = fabsf(s.x - tg.x) + fabsf(s.y - tg.y)
                 + fabsf(s.z - tg.z) + fabsf(s.w - tg.w);
        float lx = fmaxf(s.x, tg.x), ly = fmaxf(s.y, tg.y);
        float rx = fminf(s.z, tg.z), ry = fminf(s.w, tg.w);
        float w_ = fmaxf(rx - lx, 0.f), h_ = fmaxf(ry - ly, 0.f);
        float inter = w_ * h_;
        float areas = (s.z - s.x) * (s.w - s.y);
        float areat = (tg.z - tg.x) * (tg.w - tg.y);
        float uni = areas + areat - inter;
        float iou = inter / uni;
        float lx2 = fminf(s.x, tg.x), ly2 = fminf(s.y, tg.y);
        float rx2 = fmaxf(s.z, tg.z), ry2 = fmaxf(s.w, tg.w);
        float ac  = (rx2 - lx2) * (ry2 - ly2);
        sbbv[j] = l1;
        sggv[j] = 1.f - (iou - (ac - uni) / ac);
    }

    // ---- CE / focal: warp-cooperative, lanes own classes {l, l+32, l+64} ----
    const float* cpb = cp + (size_t)b * NN * DD;
    float aflbg = 0.f, aflfg = 0.f, acbg = 0.f;
    #pragma unroll 4
    for (int r = 0; r < 32; r++) {
        int i = wid * 32 + r;
        const float* row = cpb + (size_t)i * DD;
        float x0 = row[lane];
        float x1 = row[32 + lane];
        float x2 = (lane < 17) ? row[64 + lane] : -3.0e38f;
        float m = fmaxf(fmaxf(x0, x1), x2);
        #pragma unroll
        for (int o = 16; o; o >>= 1) m = fmaxf(m, __shfl_xor_sync(0xffffffffu, m, o));
        float e0 = __expf(x0 - m);
        float e1 = __expf(x1 - m);
        float e2 = (lane < 17) ? __expf(x2 - m) : 0.f;
        float s = e0 + e1 + e2;
        #pragma unroll
        for (int o = 16; o; o >>= 1) s += __shfl_xor_sync(0xffffffffu, s, o);
        int t = stc[i];
        float valx = (t < 32) ? x0 : (t < 64) ? x1 : x2;
        float xt = __shfl_sync(0xffffffffu, valx, t & 31);
        float vale = (t < 32) ? e0 : (t < 64) ? e1 : e2;
        float et = __shfl_sync(0xffffffffu, vale, t & 31);
        float ce = __logf(s) - (xt - m);
        float p  = et / s;                      // exp(-ce)
        float fl = (1.f - p) * (1.f - p) * ce;
        if (t == BG) { aflbg += 0.1f * fl; acbg += 1.f; }
        else         { aflfg += fl; }
    }
    if (lane == 0) {   // all lanes hold identical sums
        atomicAdd(&sf[0], aflbg);
        atomicAdd(&sf[1], aflfg);
        atomicAdd(&sf[2], acbg);
    }

    // ---- push/pull column sums: register accumulators per lane-class ----
    const float* eb = emb + (size_t)b * NN * DD;
    float aS0 = 0.f, aS1 = 0.f, aS2 = 0.f;
    float aP0 = 0.f, aP1 = 0.f, aP2 = 0.f;
    int   aC0 = 0,   aC1 = 0,   aC2 = 0;
    #pragma unroll 4
    for (int r = 0; r < 32; r++) {
        int i = wid * 32 + r;
        const float* row = eb + (size_t)i * DD;
        float y0 = row[lane];
        float y1 = row[32 + lane];
        float y2 = (lane < 17) ? row[64 + lane] : 0.f;
        float ss = y0*y0 + y1*y1 + y2*y2;
        #pragma unroll
        for (int o = 16; o; o >>= 1) ss += __shfl_xor_sync(0xffffffffu, ss, o);
        float inv = rsqrtf(fmaxf(ss, 1e-24f));
        int t = stc[i];
        float e0 = y0 * inv, e1 = y1 * inv, e2 = y2 * inv;
        if (t == lane)      { aP0 += 1.f - e0; aC0++; } else { aS0 += fmaxf(e0 - 0.5f, 0.f); }
        if (t == lane + 32) { aP1 += 1.f - e1; aC1++; } else { aS1 += fmaxf(e1 - 0.5f, 0.f); }
        if (lane < 17) {
            if (t == lane + 64) { aP2 += 1.f - e2; aC2++; } else { aS2 += fmaxf(e2 - 0.5f, 0.f); }
        }
    }
    sWS[wid][lane]      = aS0;  sWP[wid][lane]      = aP0;  sWC[wid][lane]      = aC0;
    sWS[wid][lane + 32] = aS1;  sWP[wid][lane + 32] = aP1;  sWC[wid][lane + 32] = aC1;
    if (lane < 17) {
        sWS[wid][lane + 64] = aS2;  sWP[wid][lane + 64] = aP2;  sWC[wid][lane + 64] = aC2;
    }
    __syncthreads();

    // ---- per-batch partial write-out ----
    if (j < DD) {
        float S = 0.f, P = 0.f; int C = 0;
        #pragma unroll
        for (int w = 0; w < NW; w++) { S += sWS[w][j]; P += sWP[w][j]; C += sWC[w][j]; }
        g_S[b][j] = S;  g_P[b][j] = P;  g_C[b][j] = C;
    }
    if (j == 0) {
        float cb = sf[2];
        g_ce[b] = sf[0] / cb + sf[1] / ((float)NN - cb);
        float bbs = 0.f, gis = 0.f;
        #pragma unroll
        for (int m = 0; m < MM; m++) { bbs += sbbv[m]; gis += sggv[m]; }
        g_bb[b] = bbs;  g_gi[b] = gis;
    }

    // ---- grid sync: last block finalizes ----
    __threadfence();
    __syncthreads();
    if (j == 0) {
        unsigned old = atomicInc(&g_tick, BB - 1u);   // wraps 15 -> 0 (self-reset)
        slast = (old == BB - 1u) ? 1 : 0;
    }
    __syncthreads();
    if (!slast) return;
    __threadfence();

    if (j < 3) racc[j] = 0.f;
    __syncthreads();
    if (j < DD) {
        float C = 0.f, P = 0.f, S = 0.f;
        #pragma unroll
        for (int b2 = 0; b2 < BB; b2++) {
            C += (float)g_C[b2][j];
            P += g_P[b2][j];
            S += g_S[b2][j];
        }
        atomicAdd(&racc[0], C * C);
        atomicAdd(&racc[1], C * P);
        atomicAdd(&racc[2], C * S);
    }
    __syncthreads();
    if (j == 0) {
        float ces = 0.f, bbs = 0.f, gis = 0.f;
        #pragma unroll
        for (int b2 = 0; b2 < BB; b2++) { ces += g_ce[b2]; bbs += g_bb[b2]; gis += g_gi[b2]; }
        float pc = racc[0];
        float T  = (float)(BB * NN);
        float nc = T * T - pc;
        out[0] = ces / (float)BB;
        out[1] = (racc[1] / pc + racc[2] / nc) / (float)BB;
        out[2] = bbs / (float)(BB * MM);
        out[3] = gis / (float)(BB * MM);
    }
}

extern "C" void kernel_launch(void* const* d_in, const int* in_sizes, int n_in,
                              void* d_out, int out_size)
{
    const float* emb = (const float*)d_in[0];   // image_embeddings
    const float* cp  = (const float*)d_in[1];   // class_predictions
    const float* pb  = (const float*)d_in[2];   // pred_boxes
    const float* tb  = (const float*)d_in[3];   // target_boxes
    const int*   tl  = (const int*)  d_in[4];   // target_labels
    const int*   mi  = (const int*)  d_in[5];   // match_idx
    float* out = (float*)d_out;

    k_all<<<BB, NN>>>(emb, cp, pb, tb, tl, mi, out);
}